// round 13
// baseline (speedup 1.0000x reference)
#include <cuda_runtime.h>
#include <cuda_fp16.h>
#include <cooperative_groups.h>
#include <math.h>

namespace cg = cooperative_groups;

#define Nn 100000
#define Ee 1600000
#define Kin 128
#define Dd 256
#define CSB 148   // cooperative scan/scatter blocks

// ---------------- scratch (device globals: no allocation allowed) ----------
__device__ __half g_h16[(size_t)Nn * Dd];     // 51.2 MB projected features (fp16, L2-resident)
__device__ float g_as_t[4 * Nn];              // a_src, head-major [h][n]
__device__ float g_ad_t[4 * Nn];              // a_dst, head-major [h][n]
__device__ int   g_deg[Nn];                   // zero-init; coop kernel re-zeroes
__device__ int   g_off[Nn + 1];
__device__ int   g_cur[Nn];
__device__ __align__(16) int g_csr[Ee];       // src ids grouped by dst
__device__ int   g_bsum[CSB];
__device__ int   g_boff[CSB];

// ---------------- helpers ---------------------------------------------------
__device__ __forceinline__ float lrelu(float v) { return fmaxf(v, 0.2f * v); }
__device__ __forceinline__ void accum8(float* acc, const uint4& hv, float a) {
    float2 f;
    f = __half22float2(*(const __half2*)&hv.x); acc[0] += f.x * a; acc[1] += f.y * a;
    f = __half22float2(*(const __half2*)&hv.y); acc[2] += f.x * a; acc[3] += f.y * a;
    f = __half22float2(*(const __half2*)&hv.z); acc[4] += f.x * a; acc[5] += f.y * a;
    f = __half22float2(*(const __half2*)&hv.w); acc[6] += f.x * a; acc[7] += f.y * a;
}
__device__ __forceinline__ unsigned int to_tf32(float f) {
    unsigned int r;
    asm("cvt.rna.tf32.f32 %0, %1;" : "=r"(r) : "f"(f));
    return r;
}
__device__ __forceinline__ void mma_tf32(float* c,
                                         const unsigned int* a,
                                         const unsigned int* b) {
    asm volatile(
        "mma.sync.aligned.m16n8k8.row.col.f32.tf32.tf32.f32 "
        "{%0,%1,%2,%3}, {%4,%5,%6,%7}, {%8,%9}, {%0,%1,%2,%3};"
        : "+f"(c[0]), "+f"(c[1]), "+f"(c[2]), "+f"(c[3])
        : "r"(a[0]), "r"(a[1]), "r"(a[2]), "r"(a[3]),
          "r"(b[0]), "r"(b[1]));
}

// ---------------- cooperative degree + scan + scatter -----------------------
__global__ void scanscatter_kernel(const int* __restrict__ ei) {
    cg::grid_group grid = cg::this_grid();
    const int b = blockIdx.x, t = threadIdx.x;
    const int NPB = (Nn + CSB - 1) / CSB;      // 676 nodes per block
    const int n0 = b * NPB;
    const int n1 = min(n0 + NPB, Nn);
    const int gstride = CSB * 1024;

    __shared__ int sscan[1024];
    __shared__ int sb[CSB + 1];

    // phase 0: degree count (coalesced grid-strided atomics)
    for (int e = b * 1024 + t; e < Ee; e += gstride)
        atomicAdd(&g_deg[ei[Ee + e]], 1);
    grid.sync();

    // phase 1: block-local degree sum (coalesced reads)
    int v = 0;
    for (int idx = n0 + t; idx < n1; idx += 1024) v += g_deg[idx];
    sscan[t] = v;
    __syncthreads();
    for (int off = 512; off; off >>= 1) {
        if (t < off) sscan[t] += sscan[t + off];
        __syncthreads();
    }
    if (t == 0) g_bsum[b] = sscan[0];
    grid.sync();

    // phase 2: block 0 scans the per-block sums (exclusive)
    if (b == 0) {
        if (t < CSB) sb[t] = g_bsum[t];
        __syncthreads();
        if (t == 0) {
            int run = 0;
            for (int i = 0; i < CSB; ++i) { int x = sb[i]; sb[i] = run; run += x; }
            sb[CSB] = run;
        }
        __syncthreads();
        if (t < CSB) g_boff[t] = sb[t];
        if (t == 0) g_off[Nn] = sb[CSB];
    }
    grid.sync();

    // phase 3: per-node exclusive scan within block (coalesced tiles)
    int run = g_boff[b];
    for (int base = n0; base < n1; base += 1024) {
        const int idx = base + t;
        const int d = (idx < n1) ? g_deg[idx] : 0;
        sscan[t] = d;
        __syncthreads();
        for (int off = 1; off < 1024; off <<= 1) {
            int add = (t >= off) ? sscan[t - off] : 0;
            __syncthreads();
            sscan[t] += add;
            __syncthreads();
        }
        if (idx < n1) {
            const int excl = run + sscan[t] - d;
            g_off[idx] = excl;
            g_cur[idx] = excl;
            g_deg[idx] = 0;   // ready for next call (zero-init covers call #1)
        }
        const int tot = sscan[1023];
        __syncthreads();
        run += tot;
    }
    grid.sync();

    // phase 4: scatter (coalesced edge reads, grid-strided)
    for (int e = b * 1024 + t; e < Ee; e += gstride) {
        const int s = ei[e];
        const int d2 = ei[Ee + e];
        const int pos = atomicAdd(&g_cur[d2], 1);
        g_csr[pos] = s;
    }
}

// ---------------- tf32 tensor GEMM + fused attention dots -------------------
// tf32 conversion happens ONCE at smem-store; MMA loop is pure LDS->HMMA.
__global__ __launch_bounds__(256, 2)
void gemm_att_kernel(const float* __restrict__ x, const float* __restrict__ W,
                     const float* __restrict__ att_src,
                     const float* __restrict__ att_dst) {
    __shared__ unsigned int xs[128][36];   // [m][k]  tf32 bits
    __shared__ unsigned int ws[32][136];   // [k][n]  tf32 bits
    const int m0 = blockIdx.x * 128;
    const int c0 = blockIdx.y * 128;
    const int tid = threadIdx.x;
    const int warp = tid >> 5, lane = tid & 31;
    const int g = lane >> 2, tig = lane & 3;
    const int wm = (warp & 3) * 32;
    const int wn = (warp >> 2) * 64;

    float acc[2][8][4];
    #pragma unroll
    for (int mt = 0; mt < 2; ++mt)
        #pragma unroll
        for (int nn = 0; nn < 8; ++nn)
            #pragma unroll
            for (int j = 0; j < 4; ++j) acc[mt][nn][j] = 0.f;

    const int xr = tid >> 1, xc = (tid & 1) * 16;
    const int wk = tid >> 3, wc = (tid & 7) * 16;

    for (int kt = 0; kt < 4; ++kt) {
        float4 xv[4], wv[4];
        #pragma unroll
        for (int i = 0; i < 4; ++i) {
            xv[i] = make_float4(0.f, 0.f, 0.f, 0.f);
            if (m0 + xr < Nn)
                xv[i] = *(const float4*)(x + (size_t)(m0 + xr) * Kin + kt * 32 + xc + i * 4);
            wv[i] = *(const float4*)(W + (size_t)(kt * 32 + wk) * Dd + c0 + wc + i * 4);
        }
        __syncthreads();
        #pragma unroll
        for (int i = 0; i < 4; ++i) {
            uint4 xt, wt;
            xt.x = to_tf32(xv[i].x); xt.y = to_tf32(xv[i].y);
            xt.z = to_tf32(xv[i].z); xt.w = to_tf32(xv[i].w);
            wt.x = to_tf32(wv[i].x); wt.y = to_tf32(wv[i].y);
            wt.z = to_tf32(wv[i].z); wt.w = to_tf32(wv[i].w);
            *(uint4*)&xs[xr][xc + i * 4] = xt;
            *(uint4*)&ws[wk][wc + i * 4] = wt;
        }
        __syncthreads();

        #pragma unroll
        for (int ks = 0; ks < 4; ++ks) {
            const int kb = ks * 8;
            unsigned int a[2][4], b[8][2];
            #pragma unroll
            for (int mt = 0; mt < 2; ++mt) {
                const int r = wm + mt * 16 + g;
                a[mt][0] = xs[r][kb + tig];
                a[mt][1] = xs[r + 8][kb + tig];
                a[mt][2] = xs[r][kb + tig + 4];
                a[mt][3] = xs[r + 8][kb + tig + 4];
            }
            #pragma unroll
            for (int nn = 0; nn < 8; ++nn) {
                const int c = wn + nn * 8 + g;
                b[nn][0] = ws[kb + tig][c];
                b[nn][1] = ws[kb + tig + 4][c];
            }
            #pragma unroll
            for (int mt = 0; mt < 2; ++mt)
                #pragma unroll
                for (int nn = 0; nn < 8; ++nn)
                    mma_tf32(acc[mt][nn], a[mt], b[nn]);
        }
    }

    const int head = blockIdx.y * 2 + (warp >> 2);
    #pragma unroll
    for (int mt = 0; mt < 2; ++mt) {
        const int r0 = m0 + wm + mt * 16 + g;
        const int r1 = r0 + 8;
        float s0 = 0.f, d0 = 0.f, s1 = 0.f, d1 = 0.f;
        #pragma unroll
        for (int nn = 0; nn < 8; ++nn) {
            const int cl = nn * 8 + tig * 2;
            const float as0 = att_src[head * 64 + cl];
            const float as1 = att_src[head * 64 + cl + 1];
            const float ad0 = att_dst[head * 64 + cl];
            const float ad1 = att_dst[head * 64 + cl + 1];
            const float* cc = acc[mt][nn];
            s0 += cc[0] * as0 + cc[1] * as1;
            d0 += cc[0] * ad0 + cc[1] * ad1;
            s1 += cc[2] * as0 + cc[3] * as1;
            d1 += cc[2] * ad0 + cc[3] * ad1;
            const int gc = c0 + wn + cl;
            if (r0 < Nn)
                *(__half2*)(g_h16 + (size_t)r0 * Dd + gc) = __floats2half2_rn(cc[0], cc[1]);
            if (r1 < Nn)
                *(__half2*)(g_h16 + (size_t)r1 * Dd + gc) = __floats2half2_rn(cc[2], cc[3]);
        }
        #pragma unroll
        for (int o = 1; o <= 2; o <<= 1) {
            s0 += __shfl_xor_sync(0xffffffffu, s0, o);
            d0 += __shfl_xor_sync(0xffffffffu, d0, o);
            s1 += __shfl_xor_sync(0xffffffffu, s1, o);
            d1 += __shfl_xor_sync(0xffffffffu, d1, o);
        }
        if (tig == 0) {
            if (r0 < Nn) { g_as_t[head * Nn + r0] = s0; g_ad_t[head * Nn + r0] = d0; }
            if (r1 < Nn) { g_as_t[head * Nn + r1] = s1; g_ad_t[head * Nn + r1] = d1; }
        }
    }
}

// ---------------- single-pass gather: fp16 h + scalar attn + int4 csr -------
__global__ __launch_bounds__(256)
void gather_kernel(const float* __restrict__ bias,
                   const float* __restrict__ gamma,
                   const float* __restrict__ beta,
                   float* __restrict__ out) {
    const int w = threadIdx.x >> 5;
    const int lane = threadIdx.x & 31;
    const int n = blockIdx.x * 8 + w;
    if (n >= Nn) return;

    const int hL = lane >> 3;   // lane owns channels [lane*8, +8) = one head
    const float* asb = g_as_t + hL * Nn;     // head-major: one scalar per edge
    const float adL = g_ad_t[hL * Nn + n];
    const int off0 = g_off[n], off1 = g_off[n + 1];

    // 32-bit byte-offset addressing into h16 (row = 512 B)
    const char* hb = (const char*)g_h16 + (unsigned)lane * 16u;
    #define HROW(s) (*(const uint4*)(hb + ((unsigned)(s) << 9)))

    float acc[8] = {0.f, 0.f, 0.f, 0.f, 0.f, 0.f, 0.f, 0.f};
    float den;
    {   // self loop
        den = __expf(lrelu(asb[n] + adL));
        accum8(acc, HROW(n), den);
    }

    int i = off0;
    // peel to 16B alignment for int4 csr loads
    while (i < off1 && (i & 3)) {
        const int src = g_csr[i++];
        const float a = __expf(lrelu(asb[src] + adL));
        den += a;
        accum8(acc, HROW(src), a);
    }
    for (; i + 4 <= off1; i += 4) {
        const int4 c = *(const int4*)(g_csr + i);
        const float q0 = asb[c.x], q1 = asb[c.y], q2 = asb[c.z], q3 = asb[c.w];
        const uint4 v0 = HROW(c.x);
        const uint4 v1 = HROW(c.y);
        const uint4 v2 = HROW(c.z);
        const uint4 v3 = HROW(c.w);
        const float a0 = __expf(lrelu(q0 + adL));
        const float a1 = __expf(lrelu(q1 + adL));
        const float a2 = __expf(lrelu(q2 + adL));
        const float a3 = __expf(lrelu(q3 + adL));
        den += a0 + a1 + a2 + a3;
        accum8(acc, v0, a0);
        accum8(acc, v1, a1);
        accum8(acc, v2, a2);
        accum8(acc, v3, a3);
    }
    for (; i < off1; ++i) {
        const int src = g_csr[i];
        const float a = __expf(lrelu(asb[src] + adL));
        den += a;
        accum8(acc, HROW(src), a);
    }
    #undef HROW

    const float rdL = 1.f / den;

    // ---- epilogue: bias + ELU + LayerNorm ----
    const float4 b0 = *(const float4*)(bias + lane * 8);
    const float4 b1 = *(const float4*)(bias + lane * 8 + 4);
    float v[8];
    v[0] = acc[0] * rdL + b0.x; v[1] = acc[1] * rdL + b0.y;
    v[2] = acc[2] * rdL + b0.z; v[3] = acc[3] * rdL + b0.w;
    v[4] = acc[4] * rdL + b1.x; v[5] = acc[5] * rdL + b1.y;
    v[6] = acc[6] * rdL + b1.z; v[7] = acc[7] * rdL + b1.w;
    float sum = 0.f, sq = 0.f;
    #pragma unroll
    for (int j = 0; j < 8; ++j) {
        v[j] = v[j] > 0.f ? v[j] : expm1f(v[j]);
        sum += v[j];
        sq += v[j] * v[j];
    }
    #pragma unroll
    for (int o = 16; o; o >>= 1) {
        sum += __shfl_xor_sync(0xffffffffu, sum, o);
        sq  += __shfl_xor_sync(0xffffffffu, sq, o);
    }
    const float mean = sum * (1.f / 256.f);
    const float var = sq * (1.f / 256.f) - mean * mean;
    const float rstd = rsqrtf(var + 1e-5f);

    const float4 g0 = *(const float4*)(gamma + lane * 8);
    const float4 g1 = *(const float4*)(gamma + lane * 8 + 4);
    const float4 be0 = *(const float4*)(beta + lane * 8);
    const float4 be1 = *(const float4*)(beta + lane * 8 + 4);
    float4 o0, o1;
    o0.x = (v[0] - mean) * rstd * g0.x + be0.x;
    o0.y = (v[1] - mean) * rstd * g0.y + be0.y;
    o0.z = (v[2] - mean) * rstd * g0.z + be0.z;
    o0.w = (v[3] - mean) * rstd * g0.w + be0.w;
    o1.x = (v[4] - mean) * rstd * g1.x + be1.x;
    o1.y = (v[5] - mean) * rstd * g1.y + be1.y;
    o1.z = (v[6] - mean) * rstd * g1.z + be1.z;
    o1.w = (v[7] - mean) * rstd * g1.w + be1.w;
    __stcs((float4*)(out + (size_t)n * Dd + lane * 8), o0);
    __stcs((float4*)(out + (size_t)n * Dd + lane * 8 + 4), o1);
}

// ---------------- stream/event singletons (created at load, outside capture)
namespace {
struct GpuRes {
    cudaStream_t s2;
    cudaEvent_t evF, evJ;
    GpuRes() {
        cudaStreamCreateWithFlags(&s2, cudaStreamNonBlocking);
        cudaEventCreateWithFlags(&evF, cudaEventDisableTiming);
        cudaEventCreateWithFlags(&evJ, cudaEventDisableTiming);
    }
};
GpuRes g_res;
}

// ---------------------------------------------------------------------------
extern "C" void kernel_launch(void* const* d_in, const int* in_sizes, int n_in,
                              void* d_out, int out_size) {
    const float* x = (const float*)d_in[0];
    const int* ei = (const int*)d_in[1];
    const float* W = (const float*)d_in[2];
    const float* att_src = (const float*)d_in[3];
    const float* att_dst = (const float*)d_in[4];
    const float* bias = (const float*)d_in[5];
    const float* gamma = (const float*)d_in[6];
    const float* beta = (const float*)d_in[7];
    float* out = (float*)d_out;

    // fork: CSR build (single coop kernel) on side stream, concurrent with GEMM
    cudaEventRecord(g_res.evF, 0);
    cudaStreamWaitEvent(g_res.s2, g_res.evF, 0);
    {
        const int* ei_arg = ei;
        void* args[] = { (void*)&ei_arg };
        cudaLaunchCooperativeKernel((void*)scanscatter_kernel, dim3(CSB), // #1
                                    dim3(1024), args, 0, g_res.s2);
    }
    cudaEventRecord(g_res.evJ, g_res.s2);

    gemm_att_kernel<<<dim3((Nn + 127) / 128, 2), 256>>>(x, W, att_src, att_dst); // #2

    // join, then gather
    cudaStreamWaitEvent(0, g_res.evJ, 0);
    gather_kernel<<<(Nn + 7) / 8, 256>>>(bias, gamma, beta, out);               // #3
}

// round 14
// speedup vs baseline: 1.0330x; 1.0330x over previous
#include <cuda_runtime.h>
#include <cuda_fp16.h>
#include <cooperative_groups.h>
#include <math.h>

namespace cg = cooperative_groups;

#define Nn 100000
#define Ee 1600000
#define Kin 128
#define Dd 256
#define CSB 148   // cooperative scan/scatter blocks

// ---------------- scratch (device globals: no allocation allowed) ----------
__device__ __half g_h16[(size_t)Nn * Dd];     // 51.2 MB projected features (fp16, L2-resident)
__device__ float g_as_t[4 * Nn];              // a_src, head-major [h][n]
__device__ float g_ad_t[4 * Nn];              // a_dst, head-major [h][n]
__device__ int   g_deg[Nn];                   // zero-init; scanscatter re-zeroes
__device__ int   g_off[Nn + 1];
__device__ int   g_cur[Nn];
__device__ __align__(16) int g_csr[Ee];       // src ids grouped by dst
__device__ int   g_bsum[CSB];
__device__ int   g_boff[CSB];

// ---------------- helpers ---------------------------------------------------
__device__ __forceinline__ float lrelu(float v) { return fmaxf(v, 0.2f * v); }
__device__ __forceinline__ void accum8(float* acc, const uint4& hv, float a) {
    float2 f;
    f = __half22float2(*(const __half2*)&hv.x); acc[0] += f.x * a; acc[1] += f.y * a;
    f = __half22float2(*(const __half2*)&hv.y); acc[2] += f.x * a; acc[3] += f.y * a;
    f = __half22float2(*(const __half2*)&hv.z); acc[4] += f.x * a; acc[5] += f.y * a;
    f = __half22float2(*(const __half2*)&hv.w); acc[6] += f.x * a; acc[7] += f.y * a;
}
__device__ __forceinline__ unsigned int to_tf32(float f) {
    unsigned int r;
    asm("cvt.rna.tf32.f32 %0, %1;" : "=r"(r) : "f"(f));
    return r;
}
__device__ __forceinline__ void mma_tf32(float* c,
                                         const unsigned int* a,
                                         const unsigned int* b) {
    asm volatile(
        "mma.sync.aligned.m16n8k8.row.col.f32.tf32.tf32.f32 "
        "{%0,%1,%2,%3}, {%4,%5,%6,%7}, {%8,%9}, {%0,%1,%2,%3};"
        : "+f"(c[0]), "+f"(c[1]), "+f"(c[2]), "+f"(c[3])
        : "r"(a[0]), "r"(a[1]), "r"(a[2]), "r"(a[3]),
          "r"(b[0]), "r"(b[1]));
}

// ---------------- degree count ------------------------------------------------
__global__ void degree_kernel(const int* __restrict__ ei) {
    int e = blockIdx.x * blockDim.x + threadIdx.x;
    if (e < Ee) atomicAdd(&g_deg[ei[Ee + e]], 1);
}

// ---------------- cooperative scan + scatter (coalesced) --------------------
__global__ void scanscatter_kernel(const int* __restrict__ ei) {
    cg::grid_group grid = cg::this_grid();
    const int b = blockIdx.x, t = threadIdx.x;
    const int NPB = (Nn + CSB - 1) / CSB;      // 676 nodes per block
    const int n0 = b * NPB;
    const int n1 = min(n0 + NPB, Nn);

    __shared__ int sscan[1024];
    __shared__ int sb[CSB + 1];

    // phase 1: block-local degree sum (coalesced reads)
    int v = 0;
    for (int idx = n0 + t; idx < n1; idx += 1024) v += g_deg[idx];
    sscan[t] = v;
    __syncthreads();
    for (int off = 512; off; off >>= 1) {
        if (t < off) sscan[t] += sscan[t + off];
        __syncthreads();
    }
    if (t == 0) g_bsum[b] = sscan[0];
    grid.sync();

    // phase 2: block 0 scans the per-block sums (exclusive)
    if (b == 0) {
        if (t < CSB) sb[t] = g_bsum[t];
        __syncthreads();
        if (t == 0) {
            int run = 0;
            for (int i = 0; i < CSB; ++i) { int x = sb[i]; sb[i] = run; run += x; }
            sb[CSB] = run;
        }
        __syncthreads();
        if (t < CSB) g_boff[t] = sb[t];
        if (t == 0) g_off[Nn] = sb[CSB];
    }
    grid.sync();

    // phase 3: per-node exclusive scan within block (coalesced tiles)
    int run = g_boff[b];
    for (int base = n0; base < n1; base += 1024) {
        const int idx = base + t;
        const int d = (idx < n1) ? g_deg[idx] : 0;
        sscan[t] = d;
        __syncthreads();
        for (int off = 1; off < 1024; off <<= 1) {
            int add = (t >= off) ? sscan[t - off] : 0;
            __syncthreads();
            sscan[t] += add;
            __syncthreads();
        }
        if (idx < n1) {
            const int excl = run + sscan[t] - d;
            g_off[idx] = excl;
            g_cur[idx] = excl;
            g_deg[idx] = 0;   // ready for next call
        }
        const int tot = sscan[1023];
        __syncthreads();
        run += tot;
    }
    grid.sync();

    // phase 4: scatter (coalesced edge reads, grid-strided)
    const int stride = CSB * 1024;
    for (int e = b * 1024 + t; e < Ee; e += stride) {
        const int s = ei[e];
        const int d2 = ei[Ee + e];
        const int pos = atomicAdd(&g_cur[d2], 1);
        g_csr[pos] = s;
    }
}

// ---------------- tf32 tensor GEMM + fused attention dots -------------------
// Register double-buffered: tile kt+1's global loads issue before compute kt.
__global__ __launch_bounds__(256, 2)
void gemm_att_kernel(const float* __restrict__ x, const float* __restrict__ W,
                     const float* __restrict__ att_src,
                     const float* __restrict__ att_dst) {
    __shared__ float xs[128][36];   // [m][k]
    __shared__ float ws[32][136];   // [k][n]
    const int m0 = blockIdx.x * 128;
    const int c0 = blockIdx.y * 128;
    const int tid = threadIdx.x;
    const int warp = tid >> 5, lane = tid & 31;
    const int g = lane >> 2, tig = lane & 3;
    const int wm = (warp & 3) * 32;
    const int wn = (warp >> 2) * 64;

    float acc[2][8][4];
    #pragma unroll
    for (int mt = 0; mt < 2; ++mt)
        #pragma unroll
        for (int nn = 0; nn < 8; ++nn)
            #pragma unroll
            for (int j = 0; j < 4; ++j) acc[mt][nn][j] = 0.f;

    const int xr = tid >> 1, xc = (tid & 1) * 16;
    const int wk = tid >> 3, wc = (tid & 7) * 16;
    const bool xok = (m0 + xr) < Nn;

    float4 xv[4], wv[4];
    // prologue: load tile 0
    #pragma unroll
    for (int i = 0; i < 4; ++i) {
        xv[i] = make_float4(0.f, 0.f, 0.f, 0.f);
        if (xok) xv[i] = *(const float4*)(x + (size_t)(m0 + xr) * Kin + xc + i * 4);
        wv[i] = *(const float4*)(W + (size_t)wk * Dd + c0 + wc + i * 4);
    }

    for (int kt = 0; kt < 4; ++kt) {
        __syncthreads();   // previous compute done before smem overwrite
        #pragma unroll
        for (int i = 0; i < 4; ++i) {
            xs[xr][xc + i * 4 + 0] = xv[i].x;
            xs[xr][xc + i * 4 + 1] = xv[i].y;
            xs[xr][xc + i * 4 + 2] = xv[i].z;
            xs[xr][xc + i * 4 + 3] = xv[i].w;
            *(float4*)&ws[wk][wc + i * 4] = wv[i];
        }
        __syncthreads();

        // issue next tile's global loads BEFORE compute (latency overlap)
        if (kt < 3) {
            const int k0n = (kt + 1) * 32;
            #pragma unroll
            for (int i = 0; i < 4; ++i) {
                xv[i] = make_float4(0.f, 0.f, 0.f, 0.f);
                if (xok) xv[i] = *(const float4*)(x + (size_t)(m0 + xr) * Kin + k0n + xc + i * 4);
                wv[i] = *(const float4*)(W + (size_t)(k0n + wk) * Dd + c0 + wc + i * 4);
            }
        }

        #pragma unroll
        for (int ks = 0; ks < 4; ++ks) {
            const int kb = ks * 8;
            unsigned int a[2][4], b[8][2];
            #pragma unroll
            for (int mt = 0; mt < 2; ++mt) {
                const int r = wm + mt * 16 + g;
                a[mt][0] = to_tf32(xs[r][kb + tig]);
                a[mt][1] = to_tf32(xs[r + 8][kb + tig]);
                a[mt][2] = to_tf32(xs[r][kb + tig + 4]);
                a[mt][3] = to_tf32(xs[r + 8][kb + tig + 4]);
            }
            #pragma unroll
            for (int nn = 0; nn < 8; ++nn) {
                const int c = wn + nn * 8 + g;
                b[nn][0] = to_tf32(ws[kb + tig][c]);
                b[nn][1] = to_tf32(ws[kb + tig + 4][c]);
            }
            #pragma unroll
            for (int mt = 0; mt < 2; ++mt)
                #pragma unroll
                for (int nn = 0; nn < 8; ++nn)
                    mma_tf32(acc[mt][nn], a[mt], b[nn]);
        }
    }

    const int head = blockIdx.y * 2 + (warp >> 2);
    #pragma unroll
    for (int mt = 0; mt < 2; ++mt) {
        const int r0 = m0 + wm + mt * 16 + g;
        const int r1 = r0 + 8;
        float s0 = 0.f, d0 = 0.f, s1 = 0.f, d1 = 0.f;
        #pragma unroll
        for (int nn = 0; nn < 8; ++nn) {
            const int cl = nn * 8 + tig * 2;
            const float as0 = att_src[head * 64 + cl];
            const float as1 = att_src[head * 64 + cl + 1];
            const float ad0 = att_dst[head * 64 + cl];
            const float ad1 = att_dst[head * 64 + cl + 1];
            const float* cc = acc[mt][nn];
            s0 += cc[0] * as0 + cc[1] * as1;
            d0 += cc[0] * ad0 + cc[1] * ad1;
            s1 += cc[2] * as0 + cc[3] * as1;
            d1 += cc[2] * ad0 + cc[3] * ad1;
            const int gc = c0 + wn + cl;
            if (r0 < Nn)
                *(__half2*)(g_h16 + (size_t)r0 * Dd + gc) = __floats2half2_rn(cc[0], cc[1]);
            if (r1 < Nn)
                *(__half2*)(g_h16 + (size_t)r1 * Dd + gc) = __floats2half2_rn(cc[2], cc[3]);
        }
        #pragma unroll
        for (int o = 1; o <= 2; o <<= 1) {
            s0 += __shfl_xor_sync(0xffffffffu, s0, o);
            d0 += __shfl_xor_sync(0xffffffffu, d0, o);
            s1 += __shfl_xor_sync(0xffffffffu, s1, o);
            d1 += __shfl_xor_sync(0xffffffffu, d1, o);
        }
        if (tig == 0) {
            if (r0 < Nn) { g_as_t[head * Nn + r0] = s0; g_ad_t[head * Nn + r0] = d0; }
            if (r1 < Nn) { g_as_t[head * Nn + r1] = s1; g_ad_t[head * Nn + r1] = d1; }
        }
    }
}

// ---------------- single-pass gather: fp16 h + scalar attn + int4 csr -------
__global__ __launch_bounds__(256)
void gather_kernel(const float* __restrict__ bias,
                   const float* __restrict__ gamma,
                   const float* __restrict__ beta,
                   float* __restrict__ out) {
    const int w = threadIdx.x >> 5;
    const int lane = threadIdx.x & 31;
    const int n = blockIdx.x * 8 + w;
    if (n >= Nn) return;

    const int hL = lane >> 3;   // lane owns channels [lane*8, +8) = one head
    const float* asb = g_as_t + hL * Nn;     // head-major: one scalar per edge
    const float adL = g_ad_t[hL * Nn + n];
    const int off0 = g_off[n], off1 = g_off[n + 1];

    const __half* hbase = g_h16;
    const size_t laneoff = (size_t)lane * 8;

    float acc[8] = {0.f, 0.f, 0.f, 0.f, 0.f, 0.f, 0.f, 0.f};
    float den;
    {   // self loop
        den = __expf(lrelu(asb[n] + adL));
        uint4 hv = *(const uint4*)(hbase + (size_t)n * Dd + laneoff);
        accum8(acc, hv, den);
    }

    int i = off0;
    // peel to 16B alignment for int4 csr loads
    while (i < off1 && (i & 3)) {
        const int src = g_csr[i++];
        const float a = __expf(lrelu(asb[src] + adL));
        den += a;
        const uint4 hv = *(const uint4*)(hbase + (size_t)src * Dd + laneoff);
        accum8(acc, hv, a);
    }
    for (; i + 4 <= off1; i += 4) {
        const int4 c = *(const int4*)(g_csr + i);
        const float q0 = asb[c.x], q1 = asb[c.y], q2 = asb[c.z], q3 = asb[c.w];
        const uint4 v0 = *(const uint4*)(hbase + (size_t)c.x * Dd + laneoff);
        const uint4 v1 = *(const uint4*)(hbase + (size_t)c.y * Dd + laneoff);
        const uint4 v2 = *(const uint4*)(hbase + (size_t)c.z * Dd + laneoff);
        const uint4 v3 = *(const uint4*)(hbase + (size_t)c.w * Dd + laneoff);
        const float a0 = __expf(lrelu(q0 + adL));
        const float a1 = __expf(lrelu(q1 + adL));
        const float a2 = __expf(lrelu(q2 + adL));
        const float a3 = __expf(lrelu(q3 + adL));
        den += a0 + a1 + a2 + a3;
        accum8(acc, v0, a0);
        accum8(acc, v1, a1);
        accum8(acc, v2, a2);
        accum8(acc, v3, a3);
    }
    for (; i < off1; ++i) {
        const int src = g_csr[i];
        const float a = __expf(lrelu(asb[src] + adL));
        den += a;
        const uint4 hv = *(const uint4*)(hbase + (size_t)src * Dd + laneoff);
        accum8(acc, hv, a);
    }

    const float rdL = 1.f / den;

    // ---- epilogue: bias + ELU + LayerNorm ----
    const float4 b0 = *(const float4*)(bias + lane * 8);
    const float4 b1 = *(const float4*)(bias + lane * 8 + 4);
    float v[8];
    v[0] = acc[0] * rdL + b0.x; v[1] = acc[1] * rdL + b0.y;
    v[2] = acc[2] * rdL + b0.z; v[3] = acc[3] * rdL + b0.w;
    v[4] = acc[4] * rdL + b1.x; v[5] = acc[5] * rdL + b1.y;
    v[6] = acc[6] * rdL + b1.z; v[7] = acc[7] * rdL + b1.w;
    float sum = 0.f, sq = 0.f;
    #pragma unroll
    for (int j = 0; j < 8; ++j) {
        v[j] = v[j] > 0.f ? v[j] : expm1f(v[j]);
        sum += v[j];
        sq += v[j] * v[j];
    }
    #pragma unroll
    for (int o = 16; o; o >>= 1) {
        sum += __shfl_xor_sync(0xffffffffu, sum, o);
        sq  += __shfl_xor_sync(0xffffffffu, sq, o);
    }
    const float mean = sum * (1.f / 256.f);
    const float var = sq * (1.f / 256.f) - mean * mean;
    const float rstd = rsqrtf(var + 1e-5f);

    const float4 g0 = *(const float4*)(gamma + lane * 8);
    const float4 g1 = *(const float4*)(gamma + lane * 8 + 4);
    const float4 be0 = *(const float4*)(beta + lane * 8);
    const float4 be1 = *(const float4*)(beta + lane * 8 + 4);
    float4 o0, o1;
    o0.x = (v[0] - mean) * rstd * g0.x + be0.x;
    o0.y = (v[1] - mean) * rstd * g0.y + be0.y;
    o0.z = (v[2] - mean) * rstd * g0.z + be0.z;
    o0.w = (v[3] - mean) * rstd * g0.w + be0.w;
    o1.x = (v[4] - mean) * rstd * g1.x + be1.x;
    o1.y = (v[5] - mean) * rstd * g1.y + be1.y;
    o1.z = (v[6] - mean) * rstd * g1.z + be1.z;
    o1.w = (v[7] - mean) * rstd * g1.w + be1.w;
    __stcs((float4*)(out + (size_t)n * Dd + lane * 8), o0);
    __stcs((float4*)(out + (size_t)n * Dd + lane * 8 + 4), o1);
}

// ---------------- stream/event singletons (created at load, outside capture)
namespace {
struct GpuRes {
    cudaStream_t s2;
    cudaEvent_t evF, evJ;
    GpuRes() {
        cudaStreamCreateWithFlags(&s2, cudaStreamNonBlocking);
        cudaEventCreateWithFlags(&evF, cudaEventDisableTiming);
        cudaEventCreateWithFlags(&evJ, cudaEventDisableTiming);
    }
};
GpuRes g_res;
}

// ---------------------------------------------------------------------------
extern "C" void kernel_launch(void* const* d_in, const int* in_sizes, int n_in,
                              void* d_out, int out_size) {
    const float* x = (const float*)d_in[0];
    const int* ei = (const int*)d_in[1];
    const float* W = (const float*)d_in[2];
    const float* att_src = (const float*)d_in[3];
    const float* att_dst = (const float*)d_in[4];
    const float* bias = (const float*)d_in[5];
    const float* gamma = (const float*)d_in[6];
    const float* beta = (const float*)d_in[7];
    float* out = (float*)d_out;

    // fork: CSR build on side stream, concurrent with GEMM on main stream
    cudaEventRecord(g_res.evF, 0);
    cudaStreamWaitEvent(g_res.s2, g_res.evF, 0);
    degree_kernel<<<(Ee + 255) / 256, 256, 0, g_res.s2>>>(ei);            // #1
    {
        const int* ei_arg = ei;
        void* args[] = { (void*)&ei_arg };
        cudaLaunchCooperativeKernel((void*)scanscatter_kernel, dim3(CSB), // #2
                                    dim3(1024), args, 0, g_res.s2);
    }
    cudaEventRecord(g_res.evJ, g_res.s2);

    gemm_att_kernel<<<dim3((Nn + 127) / 128, 2), 256>>>(x, W, att_src, att_dst); // #3

    // join, then gather (launch #4 -> ncu capture slot)
    cudaStreamWaitEvent(0, g_res.evJ, 0);
    gather_kernel<<<(Nn + 7) / 8, 256>>>(bias, gamma, beta, out);
}

// round 15
// speedup vs baseline: 1.0406x; 1.0074x over previous
#include <cuda_runtime.h>
#include <cuda_fp16.h>
#include <cooperative_groups.h>
#include <math.h>

namespace cg = cooperative_groups;

#define Nn 100000
#define Ee 1600000
#define Kin 128
#define Dd 256
#define CSB 148   // cooperative scan/scatter blocks
#define KP 130    // padded half-stride (260 B: conflict-free, odd word count)

// ---------------- scratch (device globals: no allocation allowed) ----------
__device__ __half g_h16[(size_t)Nn * Dd];     // 51.2 MB projected features (fp16, L2-resident)
__device__ float g_as_t[4 * Nn];              // a_src, head-major [h][n]
__device__ float g_ad_t[4 * Nn];              // a_dst, head-major [h][n]
__device__ int   g_deg[Nn];                   // zero-init; scanscatter re-zeroes
__device__ int   g_off[Nn + 1];
__device__ int   g_cur[Nn];
__device__ __align__(16) int g_csr[Ee];       // src ids grouped by dst
__device__ int   g_bsum[CSB];
__device__ int   g_boff[CSB];

// ---------------- helpers ---------------------------------------------------
__device__ __forceinline__ float lrelu(float v) { return fmaxf(v, 0.2f * v); }
__device__ __forceinline__ void accum8(float* acc, const uint4& hv, float a) {
    float2 f;
    f = __half22float2(*(const __half2*)&hv.x); acc[0] += f.x * a; acc[1] += f.y * a;
    f = __half22float2(*(const __half2*)&hv.y); acc[2] += f.x * a; acc[3] += f.y * a;
    f = __half22float2(*(const __half2*)&hv.z); acc[4] += f.x * a; acc[5] += f.y * a;
    f = __half22float2(*(const __half2*)&hv.w); acc[6] += f.x * a; acc[7] += f.y * a;
}
__device__ __forceinline__ void mma_f16(float* c,
                                        const unsigned int* a,
                                        const unsigned int* b) {
    asm volatile(
        "mma.sync.aligned.m16n8k16.row.col.f32.f16.f16.f32 "
        "{%0,%1,%2,%3}, {%4,%5,%6,%7}, {%8,%9}, {%0,%1,%2,%3};"
        : "+f"(c[0]), "+f"(c[1]), "+f"(c[2]), "+f"(c[3])
        : "r"(a[0]), "r"(a[1]), "r"(a[2]), "r"(a[3]),
          "r"(b[0]), "r"(b[1]));
}

// ---------------- degree count ------------------------------------------------
__global__ void degree_kernel(const int* __restrict__ ei) {
    int e = blockIdx.x * blockDim.x + threadIdx.x;
    if (e < Ee) atomicAdd(&g_deg[ei[Ee + e]], 1);
}

// ---------------- cooperative scan + scatter (coalesced) --------------------
__global__ void scanscatter_kernel(const int* __restrict__ ei) {
    cg::grid_group grid = cg::this_grid();
    const int b = blockIdx.x, t = threadIdx.x;
    const int NPB = (Nn + CSB - 1) / CSB;      // 676 nodes per block
    const int n0 = b * NPB;
    const int n1 = min(n0 + NPB, Nn);

    __shared__ int sscan[1024];
    __shared__ int sb[CSB + 1];

    // phase 1: block-local degree sum (coalesced reads)
    int v = 0;
    for (int idx = n0 + t; idx < n1; idx += 1024) v += g_deg[idx];
    sscan[t] = v;
    __syncthreads();
    for (int off = 512; off; off >>= 1) {
        if (t < off) sscan[t] += sscan[t + off];
        __syncthreads();
    }
    if (t == 0) g_bsum[b] = sscan[0];
    grid.sync();

    // phase 2: block 0 scans the per-block sums (exclusive)
    if (b == 0) {
        if (t < CSB) sb[t] = g_bsum[t];
        __syncthreads();
        if (t == 0) {
            int run = 0;
            for (int i = 0; i < CSB; ++i) { int x = sb[i]; sb[i] = run; run += x; }
            sb[CSB] = run;
        }
        __syncthreads();
        if (t < CSB) g_boff[t] = sb[t];
        if (t == 0) g_off[Nn] = sb[CSB];
    }
    grid.sync();

    // phase 3: per-node exclusive scan within block (coalesced tiles)
    int run = g_boff[b];
    for (int base = n0; base < n1; base += 1024) {
        const int idx = base + t;
        const int d = (idx < n1) ? g_deg[idx] : 0;
        sscan[t] = d;
        __syncthreads();
        for (int off = 1; off < 1024; off <<= 1) {
            int add = (t >= off) ? sscan[t - off] : 0;
            __syncthreads();
            sscan[t] += add;
            __syncthreads();
        }
        if (idx < n1) {
            const int excl = run + sscan[t] - d;
            g_off[idx] = excl;
            g_cur[idx] = excl;
            g_deg[idx] = 0;   // ready for next call
        }
        const int tot = sscan[1023];
        __syncthreads();
        run += tot;
    }
    grid.sync();

    // phase 4: scatter (coalesced edge reads, grid-strided)
    const int stride = CSB * 1024;
    for (int e = b * 1024 + t; e < Ee; e += stride) {
        const int s = ei[e];
        const int d2 = ei[Ee + e];
        const int pos = atomicAdd(&g_cur[d2], 1);
        g_csr[pos] = s;
    }
}

// ---------------- fp16 tensor GEMM (m16n8k16) + fused attention dots --------
// Single K=128 smem tile; conversion to fp16 once at store; MMA loop is pure
// LDS->HMMA with k16 steps (half the MMAs/LDS of the tf32 k8 version).
__global__ __launch_bounds__(256, 2)
void gemm_att_kernel(const float* __restrict__ x, const float* __restrict__ W,
                     const float* __restrict__ att_src,
                     const float* __restrict__ att_dst) {
    __shared__ __half xs[128][KP];    // [m][k]
    __shared__ __half wst[128][KP];   // [n][k]  (W transposed)
    const int m0 = blockIdx.x * 128;
    const int c0 = blockIdx.y * 128;
    const int tid = threadIdx.x;
    const int warp = tid >> 5, lane = tid & 31;
    const int g = lane >> 2, tig = lane & 3;
    const int wm = (warp & 3) * 32;
    const int wn = (warp >> 2) * 64;

    float acc[2][8][4];
    #pragma unroll
    for (int mt = 0; mt < 2; ++mt)
        #pragma unroll
        for (int nn = 0; nn < 8; ++nn)
            #pragma unroll
            for (int j = 0; j < 4; ++j) acc[mt][nn][j] = 0.f;

    // ---- load x tile -> xs (fp16) ----
    {
        const int xr = tid >> 1;
        const int xcb = (tid & 1) * 64;
        const bool xok = (m0 + xr) < Nn;
        #pragma unroll
        for (int i = 0; i < 16; ++i) {
            float4 v = make_float4(0.f, 0.f, 0.f, 0.f);
            if (xok) v = *(const float4*)(x + (size_t)(m0 + xr) * Kin + xcb + i * 4);
            *(__half2*)(&xs[xr][xcb + i * 4])     = __floats2half2_rn(v.x, v.y);
            *(__half2*)(&xs[xr][xcb + i * 4 + 2]) = __floats2half2_rn(v.z, v.w);
        }
    }
    // ---- load W tile transposed -> wst (fp16) ----
    {
        const int n = tid & 127;
        const int kp0 = tid >> 7;      // 0 or 1
        #pragma unroll 8
        for (int i = 0; i < 32; ++i) {
            const int kp = kp0 + i * 2;          // 0..63
            const float w0 = W[(size_t)(2 * kp) * Dd + c0 + n];
            const float w1 = W[(size_t)(2 * kp + 1) * Dd + c0 + n];
            *(__half2*)(&wst[n][2 * kp]) = __floats2half2_rn(w0, w1);
        }
    }
    __syncthreads();

    // ---- MMA mainloop: 8 x k16 steps ----
    #pragma unroll
    for (int ks = 0; ks < 8; ++ks) {
        const int kb = ks * 16;
        unsigned int a[2][4], b[8][2];
        #pragma unroll
        for (int mt = 0; mt < 2; ++mt) {
            const int r = wm + mt * 16 + g;
            a[mt][0] = *(const unsigned int*)&xs[r][kb + 2 * tig];
            a[mt][1] = *(const unsigned int*)&xs[r + 8][kb + 2 * tig];
            a[mt][2] = *(const unsigned int*)&xs[r][kb + 2 * tig + 8];
            a[mt][3] = *(const unsigned int*)&xs[r + 8][kb + 2 * tig + 8];
        }
        #pragma unroll
        for (int nn = 0; nn < 8; ++nn) {
            const int c = wn + nn * 8 + g;
            b[nn][0] = *(const unsigned int*)&wst[c][kb + 2 * tig];
            b[nn][1] = *(const unsigned int*)&wst[c][kb + 2 * tig + 8];
        }
        #pragma unroll
        for (int mt = 0; mt < 2; ++mt)
            #pragma unroll
            for (int nn = 0; nn < 8; ++nn)
                mma_f16(acc[mt][nn], a[mt], b[nn]);
    }

    // ---- epilogue: store h16 + fused per-head attention dots ----
    const int head = blockIdx.y * 2 + (warp >> 2);
    #pragma unroll
    for (int mt = 0; mt < 2; ++mt) {
        const int r0 = m0 + wm + mt * 16 + g;
        const int r1 = r0 + 8;
        float s0 = 0.f, d0 = 0.f, s1 = 0.f, d1 = 0.f;
        #pragma unroll
        for (int nn = 0; nn < 8; ++nn) {
            const int cl = nn * 8 + tig * 2;
            const float as0 = att_src[head * 64 + cl];
            const float as1 = att_src[head * 64 + cl + 1];
            const float ad0 = att_dst[head * 64 + cl];
            const float ad1 = att_dst[head * 64 + cl + 1];
            const float* cc = acc[mt][nn];
            s0 += cc[0] * as0 + cc[1] * as1;
            d0 += cc[0] * ad0 + cc[1] * ad1;
            s1 += cc[2] * as0 + cc[3] * as1;
            d1 += cc[2] * ad0 + cc[3] * ad1;
            const int gc = c0 + wn + cl;
            if (r0 < Nn)
                *(__half2*)(g_h16 + (size_t)r0 * Dd + gc) = __floats2half2_rn(cc[0], cc[1]);
            if (r1 < Nn)
                *(__half2*)(g_h16 + (size_t)r1 * Dd + gc) = __floats2half2_rn(cc[2], cc[3]);
        }
        #pragma unroll
        for (int o = 1; o <= 2; o <<= 1) {
            s0 += __shfl_xor_sync(0xffffffffu, s0, o);
            d0 += __shfl_xor_sync(0xffffffffu, d0, o);
            s1 += __shfl_xor_sync(0xffffffffu, s1, o);
            d1 += __shfl_xor_sync(0xffffffffu, d1, o);
        }
        if (tig == 0) {
            if (r0 < Nn) { g_as_t[head * Nn + r0] = s0; g_ad_t[head * Nn + r0] = d0; }
            if (r1 < Nn) { g_as_t[head * Nn + r1] = s1; g_ad_t[head * Nn + r1] = d1; }
        }
    }
}

// ---------------- single-pass gather: fp16 h + scalar attn + int4 csr -------
__global__ __launch_bounds__(256)
void gather_kernel(const float* __restrict__ bias,
                   const float* __restrict__ gamma,
                   const float* __restrict__ beta,
                   float* __restrict__ out) {
    const int w = threadIdx.x >> 5;
    const int lane = threadIdx.x & 31;
    const int n = blockIdx.x * 8 + w;
    if (n >= Nn) return;

    const int hL = lane >> 3;   // lane owns channels [lane*8, +8) = one head
    const float* asb = g_as_t + hL * Nn;     // head-major: one scalar per edge
    const float adL = g_ad_t[hL * Nn + n];
    const int off0 = g_off[n], off1 = g_off[n + 1];

    const __half* hbase = g_h16;
    const size_t laneoff = (size_t)lane * 8;

    float acc[8] = {0.f, 0.f, 0.f, 0.f, 0.f, 0.f, 0.f, 0.f};
    float den;
    {   // self loop
        den = __expf(lrelu(asb[n] + adL));
        uint4 hv = *(const uint4*)(hbase + (size_t)n * Dd + laneoff);
        accum8(acc, hv, den);
    }

    int i = off0;
    // peel to 16B alignment for int4 csr loads
    while (i < off1 && (i & 3)) {
        const int src = g_csr[i++];
        const float a = __expf(lrelu(asb[src] + adL));
        den += a;
        const uint4 hv = *(const uint4*)(hbase + (size_t)src * Dd + laneoff);
        accum8(acc, hv, a);
    }
    for (; i + 4 <= off1; i += 4) {
        const int4 c = *(const int4*)(g_csr + i);
        const float q0 = asb[c.x], q1 = asb[c.y], q2 = asb[c.z], q3 = asb[c.w];
        const uint4 v0 = *(const uint4*)(hbase + (size_t)c.x * Dd + laneoff);
        const uint4 v1 = *(const uint4*)(hbase + (size_t)c.y * Dd + laneoff);
        const uint4 v2 = *(const uint4*)(hbase + (size_t)c.z * Dd + laneoff);
        const uint4 v3 = *(const uint4*)(hbase + (size_t)c.w * Dd + laneoff);
        const float a0 = __expf(lrelu(q0 + adL));
        const float a1 = __expf(lrelu(q1 + adL));
        const float a2 = __expf(lrelu(q2 + adL));
        const float a3 = __expf(lrelu(q3 + adL));
        den += a0 + a1 + a2 + a3;
        accum8(acc, v0, a0);
        accum8(acc, v1, a1);
        accum8(acc, v2, a2);
        accum8(acc, v3, a3);
    }
    for (; i < off1; ++i) {
        const int src = g_csr[i];
        const float a = __expf(lrelu(asb[src] + adL));
        den += a;
        const uint4 hv = *(const uint4*)(hbase + (size_t)src * Dd + laneoff);
        accum8(acc, hv, a);
    }

    const float rdL = 1.f / den;

    // ---- epilogue: bias + ELU + LayerNorm ----
    const float4 b0 = *(const float4*)(bias + lane * 8);
    const float4 b1 = *(const float4*)(bias + lane * 8 + 4);
    float v[8];
    v[0] = acc[0] * rdL + b0.x; v[1] = acc[1] * rdL + b0.y;
    v[2] = acc[2] * rdL + b0.z; v[3] = acc[3] * rdL + b0.w;
    v[4] = acc[4] * rdL + b1.x; v[5] = acc[5] * rdL + b1.y;
    v[6] = acc[6] * rdL + b1.z; v[7] = acc[7] * rdL + b1.w;
    float sum = 0.f, sq = 0.f;
    #pragma unroll
    for (int j = 0; j < 8; ++j) {
        v[j] = v[j] > 0.f ? v[j] : expm1f(v[j]);
        sum += v[j];
        sq += v[j] * v[j];
    }
    #pragma unroll
    for (int o = 16; o; o >>= 1) {
        sum += __shfl_xor_sync(0xffffffffu, sum, o);
        sq  += __shfl_xor_sync(0xffffffffu, sq, o);
    }
    const float mean = sum * (1.f / 256.f);
    const float var = sq * (1.f / 256.f) - mean * mean;
    const float rstd = rsqrtf(var + 1e-5f);

    const float4 g0 = *(const float4*)(gamma + lane * 8);
    const float4 g1 = *(const float4*)(gamma + lane * 8 + 4);
    const float4 be0 = *(const float4*)(beta + lane * 8);
    const float4 be1 = *(const float4*)(beta + lane * 8 + 4);
    float4 o0, o1;
    o0.x = (v[0] - mean) * rstd * g0.x + be0.x;
    o0.y = (v[1] - mean) * rstd * g0.y + be0.y;
    o0.z = (v[2] - mean) * rstd * g0.z + be0.z;
    o0.w = (v[3] - mean) * rstd * g0.w + be0.w;
    o1.x = (v[4] - mean) * rstd * g1.x + be1.x;
    o1.y = (v[5] - mean) * rstd * g1.y + be1.y;
    o1.z = (v[6] - mean) * rstd * g1.z + be1.z;
    o1.w = (v[7] - mean) * rstd * g1.w + be1.w;
    __stcs((float4*)(out + (size_t)n * Dd + lane * 8), o0);
    __stcs((float4*)(out + (size_t)n * Dd + lane * 8 + 4), o1);
}

// ---------------- stream/event singletons (created at load, outside capture)
namespace {
struct GpuRes {
    cudaStream_t s2;
    cudaEvent_t evF, evJ;
    GpuRes() {
        cudaStreamCreateWithFlags(&s2, cudaStreamNonBlocking);
        cudaEventCreateWithFlags(&evF, cudaEventDisableTiming);
        cudaEventCreateWithFlags(&evJ, cudaEventDisableTiming);
    }
};
GpuRes g_res;
}

// ---------------------------------------------------------------------------
extern "C" void kernel_launch(void* const* d_in, const int* in_sizes, int n_in,
                              void* d_out, int out_size) {
    const float* x = (const float*)d_in[0];
    const int* ei = (const int*)d_in[1];
    const float* W = (const float*)d_in[2];
    const float* att_src = (const float*)d_in[3];
    const float* att_dst = (const float*)d_in[4];
    const float* bias = (const float*)d_in[5];
    const float* gamma = (const float*)d_in[6];
    const float* beta = (const float*)d_in[7];
    float* out = (float*)d_out;

    // fork: CSR build on side stream, concurrent with GEMM on main stream
    cudaEventRecord(g_res.evF, 0);
    cudaStreamWaitEvent(g_res.s2, g_res.evF, 0);
    degree_kernel<<<(Ee + 255) / 256, 256, 0, g_res.s2>>>(ei);            // #1
    {
        const int* ei_arg = ei;
        void* args[] = { (void*)&ei_arg };
        cudaLaunchCooperativeKernel((void*)scanscatter_kernel, dim3(CSB), // #2
                                    dim3(1024), args, 0, g_res.s2);
    }
    cudaEventRecord(g_res.evJ, g_res.s2);

    gemm_att_kernel<<<dim3((Nn + 127) / 128, 2), 256>>>(x, W, att_src, att_dst); // #3

    // join, then gather (launch #4 -> ncu capture slot)
    cudaStreamWaitEvent(0, g_res.evJ, 0);
    gather_kernel<<<(Nn + 7) / 8, 256>>>(bias, gamma, beta, out);
}